// round 4
// baseline (speedup 1.0000x reference)
#include <cuda_runtime.h>

#define Bsz   2048
#define Ssz   64
#define DSz   128
#define Hsz   512
#define MT    64      // batch rows per CTA
#define NT    128     // N chunk
#define KT    32      // K tile
#define TH    128
#define XLD   132
#define HLD   516
#define WLD   132
#define NSPIN 32

__device__ float g_ampParts[Ssz * Bsz];
__device__ float g_phase[Bsz];

static __device__ __forceinline__ unsigned long long pk2(float lo, float hi) {
    unsigned long long r;
    asm("mov.b64 %0, {%1, %2};"
        : "=l"(r) : "r"(__float_as_uint(lo)), "r"(__float_as_uint(hi)));
    return r;
}
static __device__ __forceinline__ float2 unpk2(unsigned long long v) {
    unsigned int a, b;
    asm("mov.b64 {%0, %1}, %2;" : "=r"(a), "=r"(b) : "l"(v));
    return make_float2(__uint_as_float(a), __uint_as_float(b));
}
#define FMA2(d, a, b, c) \
    asm("fma.rn.f32x2 %0, %1, %2, %3;" : "=l"(d) : "l"(a), "l"(b), "l"(c))

static __device__ __forceinline__ float silu_f(float v) {
    return v / (1.0f + __expf(-v));
}

struct AccT { unsigned long long v[8][4]; };

// async-copy one KT x NT weight tile (global row-major, ld = Hsz) into smem buf
static __device__ __forceinline__ void load_tile_async(
    float* dst, const float* __restrict__ src, int tid)
{
#pragma unroll
    for (int j = 0; j < 8; j++) {
        int t = j * TH + tid;
        int row = t >> 5, chunk = t & 31;          // 32 x 16B chunks per 128-float row
        const float* g = src + (size_t)row * Hsz + chunk * 4;
        unsigned sa = (unsigned)__cvta_generic_to_shared(dst + row * WLD + chunk * 4);
        asm volatile("cp.async.cg.shared.global [%0], [%1], 16;" :: "r"(sa), "l"(g));
    }
}

// acc(8x8) += As[r0..r0+7][:] @ Wg[:][c0..c0+7], K = nkt*KT, double-buffered cp.async
static __device__ __forceinline__ void gemm_chunk(
    AccT& acc, const float* __restrict__ As, int ald,
    const float* __restrict__ Wg,   // global W + nc*NT, row stride Hsz
    float* Wt,                       // smem: 2 buffers of KT*WLD
    int nkt, int tid, int r0, int c0)
{
#pragma unroll
    for (int i = 0; i < 8; i++)
#pragma unroll
        for (int j = 0; j < 4; j++) acc.v[i][j] = 0ull;
    if (nkt <= 0) return;

    load_tile_async(Wt, Wg, tid);
    asm volatile("cp.async.commit_group;");

    for (int kt = 0; kt < nkt; kt++) {
        const float* cur = Wt + (kt & 1) * (KT * WLD);
        if (kt + 1 < nkt) {
            load_tile_async(Wt + ((kt + 1) & 1) * (KT * WLD),
                            Wg + (size_t)(kt + 1) * KT * Hsz, tid);
            asm volatile("cp.async.commit_group;");
            asm volatile("cp.async.wait_group 1;");
        } else {
            asm volatile("cp.async.wait_group 0;");
        }
        __syncthreads();
#pragma unroll 8
        for (int k = 0; k < KT; k++) {
            const float* w = cur + k * WLD + c0;
            float4 b0 = *reinterpret_cast<const float4*>(w);
            float4 b1 = *reinterpret_cast<const float4*>(w + 4);
            unsigned long long bp0 = pk2(b0.x, b0.y);
            unsigned long long bp1 = pk2(b0.z, b0.w);
            unsigned long long bp2 = pk2(b1.x, b1.y);
            unsigned long long bp3 = pk2(b1.z, b1.w);
#pragma unroll
            for (int i = 0; i < 8; i++) {
                float av = As[(r0 + i) * ald + k];
                unsigned long long aa = pk2(av, av);
                FMA2(acc.v[i][0], aa, bp0, acc.v[i][0]);
                FMA2(acc.v[i][1], aa, bp1, acc.v[i][1]);
                FMA2(acc.v[i][2], aa, bp2, acc.v[i][2]);
                FMA2(acc.v[i][3], aa, bp3, acc.v[i][3]);
            }
        }
        __syncthreads();
    }
}

extern __shared__ float smem[];

// grid (Bsz/MT, Ssz+1): y<Ssz -> amp site y; y==Ssz -> phase MLP
__global__ void __launch_bounds__(TH, 1) fused_kernel(
    const int* __restrict__ x,
    const float* __restrict__ W1, const float* __restrict__ b1,
    const float* __restrict__ W2, const float* __restrict__ b2,
    const float* __restrict__ W3, const float* __restrict__ b3,
    const float* __restrict__ Wp1, const float* __restrict__ bp1,
    const float* __restrict__ Wp2, const float* __restrict__ bp2,
    const float* __restrict__ Wp3, const float* __restrict__ bp3)
{
    float* Xs  = smem;                  // MT x XLD (x, then h2 chunks)
    float* Hs  = Xs + MT * XLD;         // MT x HLD
    float* Wt  = Hs + MT * HLD;         // 2 x KT x WLD
    float* W3s = Wt + 2 * KT * WLD;     // 512 x 4
    float* Ls  = W3s + Hsz * 4;         // MT x 4

    const int tid = threadIdx.x;
    const int m0  = blockIdx.x * MT;
    const int s   = blockIdx.y;
    const bool isPhase = (s == Ssz);

    // load X tile (row-major) as float
#pragma unroll
    for (int m = 0; m < 16; m++) {
        int t = m * TH + tid;
        int row = t >> 5, c4 = (t & 31) * 4;
        int4 v = *reinterpret_cast<const int4*>(x + (size_t)(m0 + row) * DSz + c4);
        Xs[row * XLD + c4 + 0] = (float)v.x;
        Xs[row * XLD + c4 + 1] = (float)v.y;
        Xs[row * XLD + c4 + 2] = (float)v.z;
        Xs[row * XLD + c4 + 3] = (float)v.w;
    }
    // load W3 (amp) or Wp3 (phase) into W3s [512][4]
    if (!isPhase) {
        const float4* src = reinterpret_cast<const float4*>(W3 + (size_t)s * Hsz * 4);
#pragma unroll
        for (int m = 0; m < 4; m++)
            reinterpret_cast<float4*>(W3s)[m * TH + tid] = src[m * TH + tid];
    } else {
        for (int i = tid; i < Hsz; i += TH) {
            W3s[i * 4 + 0] = Wp3[i];
            W3s[i * 4 + 1] = 0.f; W3s[i * 4 + 2] = 0.f; W3s[i * 4 + 3] = 0.f;
        }
    }
    __syncthreads();

    // autoregressive prefix counts + occupied bits (amp only, into registers)
    int up_e = 0, dn_e = 0, bu = 0, bd = 0;
    if (!isPhase && tid < MT) {
        const float* row = Xs + tid * XLD;
        for (int i = 0; i < s; i++) {
            up_e += (int)row[2 * i];
            dn_e += (int)row[2 * i + 1];
        }
        bu = (int)row[2 * s];
        bd = (int)row[2 * s + 1];
    }

    const int r0 = (tid >> 4) * 8;
    const int c0 = (tid & 15) * 8;

    const float* W1p = isPhase ? Wp1 : W1 + (size_t)s * DSz * Hsz;
    const float* b1p = isPhase ? bp1 : b1 + (size_t)s * Hsz;
    const float* W2p = isPhase ? Wp2 : W2 + (size_t)s * Hsz * Hsz;
    const float* b2p = isPhase ? bp2 : b2 + (size_t)s * Hsz;
    const int nkt1 = isPhase ? (DSz / KT) : (2 * s + KT - 1) / KT;

    // ---- layer 1: Hs = silu(Xs @ W1p + b1p) ----
    for (int nc = 0; nc < Hsz / NT; nc++) {
        AccT acc;
        gemm_chunk(acc, Xs, XLD, W1p + nc * NT, Wt, nkt1, tid, r0, c0);
#pragma unroll
        for (int i = 0; i < 8; i++)
#pragma unroll
            for (int j = 0; j < 4; j++) {
                float2 p = unpk2(acc.v[i][j]);
                int c = nc * NT + c0 + 2 * j;
                Hs[(r0 + i) * HLD + c]     = silu_f(p.x + b1p[c]);
                Hs[(r0 + i) * HLD + c + 1] = silu_f(p.y + b1p[c + 1]);
            }
    }

    // ---- layer 2 + fused layer 3 ----
    const int row3 = tid & 63, og = tid >> 6;
    float lg0 = 0.f, lg1 = 0.f;
    for (int nc = 0; nc < Hsz / NT; nc++) {
        AccT acc;
        gemm_chunk(acc, Hs, HLD, W2p + nc * NT, Wt, Hsz / KT, tid, r0, c0);
        // h2 chunk -> Xs (row-major [MT][NT])
#pragma unroll
        for (int i = 0; i < 8; i++)
#pragma unroll
            for (int j = 0; j < 4; j++) {
                float2 p = unpk2(acc.v[i][j]);
                int c = nc * NT + c0 + 2 * j;
                Xs[(r0 + i) * XLD + c0 + 2 * j]     = silu_f(p.x + b2p[c]);
                Xs[(r0 + i) * XLD + c0 + 2 * j + 1] = silu_f(p.y + b2p[c + 1]);
            }
        __syncthreads();
        float s0 = 0.f, s1 = 0.f;
#pragma unroll 8
        for (int k = 0; k < NT; k++) {
            float v = Xs[row3 * XLD + k];
            s0 += v * W3s[(nc * NT + k) * 4 + og * 2];
            s1 += v * W3s[(nc * NT + k) * 4 + og * 2 + 1];
        }
        lg0 += s0; lg1 += s1;
        __syncthreads();
    }
    Ls[row3 * 4 + og * 2]     = lg0;
    Ls[row3 * 4 + og * 2 + 1] = lg1;
    __syncthreads();

    if (tid < MT) {
        if (isPhase) {
            g_phase[m0 + tid] = Ls[tid * 4 + 0] + bp3[0];
        } else {
            float l0 = Ls[tid * 4 + 0] + b3[s * 4 + 0];
            float l1 = Ls[tid * 4 + 1] + b3[s * 4 + 1];
            float l2 = Ls[tid * 4 + 2] + b3[s * 4 + 2];
            float l3 = Ls[tid * 4 + 3] + b3[s * 4 + 3];
            const float NEG = -1e30f;
            bool au0 = (s - up_e) < (Ssz - NSPIN);
            bool au1 = up_e < NSPIN;
            bool ad0 = (s - dn_e) < (Ssz - NSPIN);
            bool ad1 = dn_e < NSPIN;
            float d0 = (au0 && ad0) ? l0 : NEG;
            float d1 = (au0 && ad1) ? l1 : NEG;
            float d2 = (au1 && ad0) ? l2 : NEG;
            float d3 = (au1 && ad1) ? l3 : NEG;
            float mx = fmaxf(fmaxf(d0, d1), fmaxf(d2, d3));
            float sum = expf(2.f * (d0 - mx)) + expf(2.f * (d1 - mx))
                      + expf(2.f * (d2 - mx)) + expf(2.f * (d3 - mx));
            float lse = mx + 0.5f * logf(sum);
            int idx = bu * 2 + bd;
            float dsel = (idx == 0) ? d0 : (idx == 1) ? d1 : (idx == 2) ? d2 : d3;
            g_ampParts[s * Bsz + m0 + tid] = dsel - lse;
        }
    }
}

__global__ void final_kernel(float2* __restrict__ out) {
    int b = blockIdx.x * blockDim.x + threadIdx.x;
    if (b >= Bsz) return;
    float amp = 0.f;
#pragma unroll 8
    for (int s = 0; s < Ssz; s++) amp += g_ampParts[s * Bsz + b];
    float ea = expf(amp);
    float sv, cv;
    sincosf(g_phase[b], &sv, &cv);
    out[b] = make_float2(ea * cv, ea * sv);
}

extern "C" void kernel_launch(void* const* d_in, const int* in_sizes, int n_in,
                              void* d_out, int out_size)
{
    (void)in_sizes; (void)n_in; (void)out_size;
    const int*   x   = (const int*)  d_in[0];
    const float* W1  = (const float*)d_in[1];
    const float* b1  = (const float*)d_in[2];
    const float* W2  = (const float*)d_in[3];
    const float* b2  = (const float*)d_in[4];
    const float* W3  = (const float*)d_in[5];
    const float* b3  = (const float*)d_in[6];
    const float* Wp1 = (const float*)d_in[7];
    const float* bp1 = (const float*)d_in[8];
    const float* Wp2 = (const float*)d_in[9];
    const float* bp2 = (const float*)d_in[10];
    const float* Wp3 = (const float*)d_in[11];
    const float* bp3 = (const float*)d_in[12];

    const int SMEM = (MT * XLD + MT * HLD + 2 * KT * WLD + Hsz * 4 + MT * 4) * (int)sizeof(float);
    cudaFuncSetAttribute(fused_kernel, cudaFuncAttributeMaxDynamicSharedMemorySize, SMEM);

    fused_kernel<<<dim3(Bsz / MT, Ssz + 1), TH, SMEM>>>(
        x, W1, b1, W2, b2, W3, b3, Wp1, bp1, Wp2, bp2, Wp3, bp3);
    final_kernel<<<Bsz / 256, 256>>>((float2*)d_out);
}

// round 8
// speedup vs baseline: 2.3236x; 2.3236x over previous
#include <cuda_runtime.h>
#include <cuda_bf16.h>

#define Bsz 2048
#define Ssz 64
#define MT  64
#define TH  256
#define NSPIN 32

// weight tile-pairs: [128 n][72 k] bf16 hi plane (9216 el) + lo plane = 18432 elems each
__device__ __align__(16) __nv_bfloat16 g_W1T[520ull  * 18432];
__device__ __align__(16) __nv_bfloat16 g_W2T[2080ull * 18432];
__device__ float g_parts[65 * Bsz];     // rows 0-63 amp, row 64 phase

__device__ __forceinline__ float silu_f(float v) { return v / (1.0f + __expf(-v)); }
__device__ __forceinline__ unsigned packbf(__nv_bfloat16 a, __nv_bfloat16 b) {
    return (unsigned)__bfloat16_as_ushort(a) | ((unsigned)__bfloat16_as_ushort(b) << 16);
}
#define LDSM4(r, a) asm volatile( \
    "ldmatrix.sync.aligned.m8n8.x4.shared.b16 {%0,%1,%2,%3}, [%4];" \
    : "=r"((r)[0]), "=r"((r)[1]), "=r"((r)[2]), "=r"((r)[3]) : "r"(a))
#define MMA(c, a, b) asm volatile( \
    "mma.sync.aligned.m16n8k16.row.col.f32.bf16.bf16.f32 " \
    "{%0,%1,%2,%3},{%4,%5,%6,%7},{%8,%9},{%0,%1,%2,%3};" \
    : "+f"((c)[0]), "+f"((c)[1]), "+f"((c)[2]), "+f"((c)[3]) \
    : "r"((a)[0]), "r"((a)[1]), "r"((a)[2]), "r"((a)[3]), "r"((b)[0]), "r"((b)[1]))
#define CPA(dst, src) asm volatile("cp.async.cg.shared.global [%0],[%1],16;" :: "r"(dst), "l"(src))
#define CPA_COMMIT() asm volatile("cp.async.commit_group;" ::: "memory")
#define CPA_WAIT1()  asm volatile("cp.async.wait_group 1;" ::: "memory")
#define CPA_WAIT0()  asm volatile("cp.async.wait_group 0;" ::: "memory")

// ---------- prep: transpose fp32 [k][n] -> bf16 hi/lo [n][72] tiles ----------
__global__ void prep_kernel(const float* __restrict__ W1, const float* __restrict__ Wp1,
                            const float* __restrict__ W2, const float* __restrict__ Wp2) {
    __shared__ float s[64][132];
    int b = blockIdx.x, t = threadIdx.x;
    const float* src; __nv_bfloat16* dst; int k0, n0;
    if (b < 520) {                         // W1: site*8 + nc*2 + kc
        int site = b >> 3, tt = b & 7;
        int nc = tt >> 1, kc = tt & 1;
        k0 = kc * 64; n0 = nc * 128;
        src = (site < 64) ? W1 + (size_t)site * 128 * 512 : Wp1;
        dst = g_W1T + (size_t)b * 18432;
    } else {                               // W2: site*32 + nc*8 + kc
        int bb = b - 520, site = bb >> 5, tt = bb & 31;
        int nc = tt >> 3, kc = tt & 7;
        k0 = kc * 64; n0 = nc * 128;
        src = (site < 64) ? W2 + (size_t)site * 512 * 512 : Wp2;
        dst = g_W2T + (size_t)bb * 18432;
    }
#pragma unroll
    for (int i = 0; i < 8; i++) {
        int e = i * 256 + t, kk = e >> 5, cb = (e & 31) * 4;
        *(float4*)&s[kk][cb] = *(const float4*)(src + (size_t)(k0 + kk) * 512 + n0 + cb);
    }
    __syncthreads();
    __nv_bfloat16* dl = dst + 9216;
#pragma unroll
    for (int j = 0; j < 4; j++) {
        int e = j * 256 + t, nr = e >> 3, k8 = (e & 7) * 8;
        unsigned hv[4], lv[4];
#pragma unroll
        for (int q = 0; q < 4; q++) {
            float f0 = s[k8 + 2 * q][nr], f1 = s[k8 + 2 * q + 1][nr];
            __nv_bfloat16 h0 = __float2bfloat16(f0), h1 = __float2bfloat16(f1);
            hv[q] = packbf(h0, h1);
            lv[q] = packbf(__float2bfloat16(f0 - __bfloat162float(h0)),
                           __float2bfloat16(f1 - __bfloat162float(h1)));
        }
        *(uint4*)(dst + (size_t)nr * 72 + k8) = make_uint4(hv[0], hv[1], hv[2], hv[3]);
        *(uint4*)(dl  + (size_t)nr * 72 + k8) = make_uint4(lv[0], lv[1], lv[2], lv[3]);
    }
    if (t < 128) {
        uint4 z = make_uint4(0, 0, 0, 0);
        *(uint4*)(dst + (size_t)t * 72 + 64) = z;
        *(uint4*)(dl  + (size_t)t * 72 + 64) = z;
    }
}

// ---------- main fused kernel ----------
#define SM_XS   0          // [64][136] bf16 = 17408 (W3S+LS overlay after layer1)
#define SM_W3   0          // f32 [512][4] = 8192 (overlay)
#define SM_LS   8192       // f32 [4][64][4] = 4096 (overlay)
#define SM_H1H  17408      // [64][520] bf16 = 66560
#define SM_H1L  83968
#define SM_WT   150528     // 2 x 36864 (tile-pair: hi 18432B, lo 18432B)
#define SM_B1   224256
#define SM_B2   226304
#define SM_SIZE 228352

extern __shared__ char smem[];

__global__ void __launch_bounds__(TH) main_kernel(
    const int* __restrict__ x,
    const float* __restrict__ b1, const float* __restrict__ b2,
    const float* __restrict__ W3, const float* __restrict__ b3,
    const float* __restrict__ bp1, const float* __restrict__ bp2,
    const float* __restrict__ Wp3, const float* __restrict__ bp3)
{
    const unsigned sb = (unsigned)__cvta_generic_to_shared(smem);
    const int tid = threadIdx.x, lane = tid & 31, wid = tid >> 5;
    const int wm = wid & 1, wn = wid >> 1;       // 2 m-warps x 4 n-warps
    const int m0 = blockIdx.x * MT;
    const int s = blockIdx.y;
    const bool isPh = (s == Ssz);
    __nv_bfloat16* XS  = (__nv_bfloat16*)(smem + SM_XS);
    __nv_bfloat16* H1H = (__nv_bfloat16*)(smem + SM_H1H);
    __nv_bfloat16* H1L = (__nv_bfloat16*)(smem + SM_H1L);
    float* W3s = (float*)(smem + SM_W3);
    float* Ls  = (float*)(smem + SM_LS);
    float* b1s = (float*)(smem + SM_B1);
    float* b2s = (float*)(smem + SM_B2);

    // X tile -> exact bf16 [64][136]
#pragma unroll
    for (int i = 0; i < 8; i++) {
        int e = i * 256 + tid, row = e >> 5, c4 = (e & 31) * 4;
        int4 v = *(const int4*)(x + (size_t)(m0 + row) * 128 + c4);
        unsigned lo = (v.x ? 0x3F80u : 0u) | ((v.y ? 0x3F80u : 0u) << 16);
        unsigned hi = (v.z ? 0x3F80u : 0u) | ((v.w ? 0x3F80u : 0u) << 16);
        *(uint2*)(XS + row * 136 + c4) = make_uint2(lo, hi);
    }
    const float* b1p = isPh ? bp1 : b1 + (size_t)s * 512;
    const float* b2p = isPh ? bp2 : b2 + (size_t)s * 512;
    for (int i = tid; i < 512; i += TH) { b1s[i] = b1p[i]; b2s[i] = b2p[i]; }
    __syncthreads();

    // autoregressive prefix counts (amp only)
    int up_e = 0, dn_e = 0, bu = 0, bd = 0;
    if (!isPh && tid < MT) {
        const unsigned short* row = (const unsigned short*)(XS + tid * 136);
        for (int i = 0; i < s; i++) {
            up_e += row[2 * i] ? 1 : 0;
            dn_e += row[2 * i + 1] ? 1 : 0;
        }
        bu = row[2 * s] ? 1 : 0;
        bd = row[2 * s + 1] ? 1 : 0;
    }

    const int nkt1 = (isPh || s > 32) ? 2 : 1;
    const int t1 = 4 * nkt1, T = t1 + 32;
    const size_t base1 = (size_t)(isPh ? 64 : s) * 8;
    const size_t base2 = (size_t)(isPh ? 64 : s) * 32;

#define PREFETCH(ti) do { \
        const __nv_bfloat16* g; \
        if ((ti) < t1) { int nc_ = (ti) / nkt1, kc_ = (ti) % nkt1; \
            g = g_W1T + (base1 + nc_ * 2 + kc_) * 18432; } \
        else { int u_ = (ti) - t1; g = g_W2T + (base2 + (size_t)u_) * 18432; } \
        unsigned dstb = sb + SM_WT + ((ti) & 1) * 36864; \
        _Pragma("unroll") \
        for (int j_ = 0; j_ < 9; j_++) { int ch = j_ * 256 + tid; \
            CPA(dstb + ch * 16, (const char*)g + ch * 16); } \
    } while (0)

    float acc[2][4][4];
    PREFETCH(0); CPA_COMMIT();

    for (int ti = 0; ti < T; ti++) {
        const bool l1 = ti < t1;
        int nc, kc, nkc;
        if (l1) { nc = ti / nkt1; kc = ti % nkt1; nkc = nkt1; }
        else    { int u = ti - t1; nc = u >> 3; kc = u & 7; nkc = 8; }

        if (ti + 1 < T) { PREFETCH(ti + 1); CPA_COMMIT(); CPA_WAIT1(); }
        else CPA_WAIT0();
        __syncthreads();

        if (ti == t1) {          // X dead: overlay W3S + zero Ls
            if (!isPh) {
                for (int i = tid; i < 2048; i += TH) W3s[i] = W3[(size_t)s * 2048 + i];
            } else {
                for (int i = tid; i < 512; i += TH) {
                    W3s[i * 4] = Wp3[i];
                    W3s[i * 4 + 1] = 0.f; W3s[i * 4 + 2] = 0.f; W3s[i * 4 + 3] = 0.f;
                }
            }
            for (int i = tid; i < 1024; i += TH) Ls[i] = 0.f;
            __syncthreads();
        }

        if (kc == 0) {
#pragma unroll
            for (int mi = 0; mi < 2; mi++)
#pragma unroll
                for (int ni = 0; ni < 4; ni++)
#pragma unroll
                    for (int q = 0; q < 4; q++) acc[mi][ni][q] = 0.f;
        }

        // ---- compute tile: warp tile 32x32, K chunk 64 ----
        const unsigned wtb = sb + SM_WT + (ti & 1) * 36864;
        const unsigned aH = l1 ? (sb + SM_XS) : (sb + SM_H1H);
        const unsigned aL = sb + SM_H1L;
        const int lda = l1 ? 136 : 520;
#pragma unroll
        for (int kk = 0; kk < 4; kk++) {
            unsigned a_h[2][4], a_l[2][4], b_h[4][2], b_l[4][2], tmp[4];
            int acol = kc * 64 + kk * 16 + (lane >> 4) * 8;
#pragma unroll
            for (int mi = 0; mi < 2; mi++) {
                int ar = wm * 32 + mi * 16 + (lane & 15);
                LDSM4(a_h[mi], aH + (unsigned)(ar * lda + acol) * 2);
                if (!l1) LDSM4(a_l[mi], aL + (unsigned)(ar * lda + acol) * 2);
            }
            int bcol = kk * 16 + (lane >> 4) * 8;
#pragma unroll
            for (int nh = 0; nh < 2; nh++) {
                int br = wn * 32 + nh * 16 + (lane & 15);
                unsigned ba = wtb + (unsigned)(br * 72 + bcol) * 2;
                LDSM4(tmp, ba);
                b_h[nh * 2][0] = tmp[0]; b_h[nh * 2][1] = tmp[2];
                b_h[nh * 2 + 1][0] = tmp[1]; b_h[nh * 2 + 1][1] = tmp[3];
                LDSM4(tmp, ba + 18432);
                b_l[nh * 2][0] = tmp[0]; b_l[nh * 2][1] = tmp[2];
                b_l[nh * 2 + 1][0] = tmp[1]; b_l[nh * 2 + 1][1] = tmp[3];
            }
#pragma unroll
            for (int mi = 0; mi < 2; mi++)
#pragma unroll
                for (int ni = 0; ni < 4; ni++) {
                    MMA(acc[mi][ni], a_h[mi], b_h[ni]);
                    MMA(acc[mi][ni], a_h[mi], b_l[ni]);
                    if (!l1) MMA(acc[mi][ni], a_l[mi], b_h[ni]);
                }
        }

        // ---- chunk epilogues ----
        if (kc == nkc - 1) {
            if (l1) {
#pragma unroll
                for (int mi = 0; mi < 2; mi++)
#pragma unroll
                    for (int ni = 0; ni < 4; ni++) {
                        int r = wm * 32 + mi * 16 + (lane >> 2);
                        int c = nc * 128 + wn * 32 + ni * 8 + (lane & 3) * 2;
#pragma unroll
                        for (int h = 0; h < 2; h++) {
                            int rr = r + h * 8;
                            float v0 = silu_f(acc[mi][ni][2 * h]     + b1s[c]);
                            float v1 = silu_f(acc[mi][ni][2 * h + 1] + b1s[c + 1]);
                            __nv_bfloat16 h0 = __float2bfloat16(v0), h1 = __float2bfloat16(v1);
                            *(unsigned*)(H1H + rr * 520 + c) = packbf(h0, h1);
                            *(unsigned*)(H1L + rr * 520 + c) =
                                packbf(__float2bfloat16(v0 - __bfloat162float(h0)),
                                       __float2bfloat16(v1 - __bfloat162float(h1)));
                        }
                    }
            } else {
                float p[4][4];
#pragma unroll
                for (int j = 0; j < 4; j++)
#pragma unroll
                    for (int o = 0; o < 4; o++) p[j][o] = 0.f;
#pragma unroll
                for (int mi = 0; mi < 2; mi++)
#pragma unroll
                    for (int ni = 0; ni < 4; ni++) {
                        int c = nc * 128 + wn * 32 + ni * 8 + (lane & 3) * 2;
                        float4 w0 = *(float4*)&W3s[c * 4];
                        float4 w1 = *(float4*)&W3s[(c + 1) * 4];
#pragma unroll
                        for (int h = 0; h < 2; h++) {
                            float v0 = silu_f(acc[mi][ni][2 * h]     + b2s[c]);
                            float v1 = silu_f(acc[mi][ni][2 * h + 1] + b2s[c + 1]);
                            int j = mi * 2 + h;
                            p[j][0] += v0 * w0.x + v1 * w1.x;
                            p[j][1] += v0 * w0.y + v1 * w1.y;
                            p[j][2] += v0 * w0.z + v1 * w1.z;
                            p[j][3] += v0 * w0.w + v1 * w1.w;
                        }
                    }
#pragma unroll
                for (int j = 0; j < 4; j++)
#pragma unroll
                    for (int o = 0; o < 4; o++) {
                        p[j][o] += __shfl_xor_sync(0xFFFFFFFFu, p[j][o], 1);
                        p[j][o] += __shfl_xor_sync(0xFFFFFFFFu, p[j][o], 2);
                    }
                if ((lane & 3) == 0) {
                    int q = lane >> 2;
#pragma unroll
                    for (int j = 0; j < 4; j++) {
                        int r = wm * 32 + (j >> 1) * 16 + (j & 1) * 8 + q;
                        float* dst = &Ls[(wn * 64 + r) * 4];
#pragma unroll
                        for (int o = 0; o < 4; o++) dst[o] += p[j][o];
                    }
                }
            }
        }
    }
    __syncthreads();

    if (tid < MT) {
        float l0 = Ls[tid * 4 + 0] + Ls[(64 + tid) * 4 + 0] + Ls[(128 + tid) * 4 + 0] + Ls[(192 + tid) * 4 + 0];
        float l1v = Ls[tid * 4 + 1] + Ls[(64 + tid) * 4 + 1] + Ls[(128 + tid) * 4 + 1] + Ls[(192 + tid) * 4 + 1];
        float l2 = Ls[tid * 4 + 2] + Ls[(64 + tid) * 4 + 2] + Ls[(128 + tid) * 4 + 2] + Ls[(192 + tid) * 4 + 2];
        float l3 = Ls[tid * 4 + 3] + Ls[(64 + tid) * 4 + 3] + Ls[(128 + tid) * 4 + 3] + Ls[(192 + tid) * 4 + 3];
        if (isPh) {
            g_parts[64 * Bsz + m0 + tid] = l0 + bp3[0];
        } else {
            l0 += b3[s * 4 + 0]; l1v += b3[s * 4 + 1];
            l2 += b3[s * 4 + 2]; l3 += b3[s * 4 + 3];
            const float NEG = -1e30f;
            bool au0 = (s - up_e) < (Ssz - NSPIN), au1 = up_e < NSPIN;
            bool ad0 = (s - dn_e) < (Ssz - NSPIN), ad1 = dn_e < NSPIN;
            float d0 = (au0 && ad0) ? l0 : NEG;
            float d1 = (au0 && ad1) ? l1v : NEG;
            float d2 = (au1 && ad0) ? l2 : NEG;
            float d3 = (au1 && ad1) ? l3 : NEG;
            float mx = fmaxf(fmaxf(d0, d1), fmaxf(d2, d3));
            float sum = expf(2.f * (d0 - mx)) + expf(2.f * (d1 - mx))
                      + expf(2.f * (d2 - mx)) + expf(2.f * (d3 - mx));
            float lse = mx + 0.5f * logf(sum);
            int idx = bu * 2 + bd;
            float dsel = (idx == 0) ? d0 : (idx == 1) ? d1 : (idx == 2) ? d2 : d3;
            g_parts[s * Bsz + m0 + tid] = dsel - lse;
        }
    }
}

__global__ void final_kernel(float2* __restrict__ out) {
    int b = blockIdx.x * blockDim.x + threadIdx.x;
    if (b >= Bsz) return;
    float amp = 0.f;
#pragma unroll 8
    for (int s = 0; s < Ssz; s++) amp += g_parts[s * Bsz + b];
    float ea = expf(amp);
    float sv, cv;
    sincosf(g_parts[64 * Bsz + b], &sv, &cv);
    out[b] = make_float2(ea * cv, ea * sv);
}

extern "C" void kernel_launch(void* const* d_in, const int* in_sizes, int n_in,
                              void* d_out, int out_size)
{
    (void)in_sizes; (void)n_in; (void)out_size;
    const int*   x   = (const int*)  d_in[0];
    const float* W1  = (const float*)d_in[1];
    const float* b1  = (const float*)d_in[2];
    const float* W2  = (const float*)d_in[3];
    const float* b2  = (const float*)d_in[4];
    const float* W3  = (const float*)d_in[5];
    const float* b3  = (const float*)d_in[6];
    const float* Wp1 = (const float*)d_in[7];
    const float* bp1 = (const float*)d_in[8];
    const float* Wp2 = (const float*)d_in[9];
    const float* bp2 = (const float*)d_in[10];
    const float* Wp3 = (const float*)d_in[11];
    const float* bp3 = (const float*)d_in[12];

    prep_kernel<<<2600, 256>>>(W1, Wp1, W2, Wp2);
    cudaFuncSetAttribute(main_kernel, cudaFuncAttributeMaxDynamicSharedMemorySize, SM_SIZE);
    main_kernel<<<dim3(Bsz / MT, Ssz + 1), TH, SM_SIZE>>>(
        x, b1, b2, W3, b3, bp1, bp2, Wp3, bp3);
    final_kernel<<<Bsz / 256, 256>>>((float2*)d_out);
}